// round 14
// baseline (speedup 1.0000x reference)
#include <cuda_runtime.h>
#include <cuda_bf16.h>
#include <cstdint>
#include <math.h>

// ---------------------------------------------------------------- shapes
#define BB 2
#define NN 5
#define KSHOT 5
#define QQ 75
#define TT 196
#define CC 384
#define SS 980
#define M_REAL (QQ*TT)      // 14700
#define M_PAD  14720        // 115*128, padded rows zero (BSS)
#define S_PAD  1024         // 8*128, padded rows zero (BSS)
#define M_TILES 115
#define S_TILES 8
#define KCH 6               // K chunks of 64 bf16 (128B rows, SW128 atoms)
#define NCHUNK (S_TILES*KCH)  // 48 B chunks
#define BATCH 4             // chunks per sync event
#define NB (NCHUNK/BATCH)   // 12 batches
#define NSTAGE 8            // B ring stages (2 batches resident)
#define TEMP_V 10.0f

// Canonical SW128 layout: 128 rows x 128B per chunk.
#define CHUNK_B 16384                      // 128 * 128
#define A_OFF   0
#define B_OFF   (KCH*CHUNK_B)              // 98304 (A resident: 96KB)
#define RED_OFF (B_OFF + NSTAGE*CHUNK_B)   // 229376
#define SMEM_TOTAL (RED_OFF + 4*128*4)     // 231424 (<= 232448 max dyn)

// normalized bf16 scratch, zero-padded (BSS zero-init)
__device__ __nv_bfloat16 g_fq[(size_t)BB*M_PAD*CC];
__device__ __nv_bfloat16 g_fs[(size_t)BB*NN*S_PAD*CC];

// ---------------------------------------------------------------- helpers
__device__ __forceinline__ uint32_t smem_u32(const void* p) {
    uint32_t a;
    asm("{ .reg .u64 t; cvta.to.shared.u64 t, %1; cvt.u32.u64 %0, t; }"
        : "=r"(a) : "l"(p));
    return a;
}
#define SWZ(off) ((off) ^ (((off) >> 3) & 0x70))

#define CP_ASYNC16(dst, gsrc) \
    asm volatile("cp.async.cg.shared.global [%0], [%1], 16;" :: "r"(dst), "l"(gsrc) : "memory")
#define CP_COMMIT() asm volatile("cp.async.commit_group;" ::: "memory")
#define CP_WAITN(n) asm volatile("cp.async.wait_group %0;" :: "n"(n) : "memory")

__device__ __forceinline__ void ldsm4(uint32_t (&r)[4], uint32_t addr) {
    asm volatile("ldmatrix.sync.aligned.m8n8.x4.shared.b16 {%0,%1,%2,%3}, [%4];"
        : "=r"(r[0]), "=r"(r[1]), "=r"(r[2]), "=r"(r[3]) : "r"(addr));
}
__device__ __forceinline__ void mma16816(float (&d)[4], const uint32_t (&a)[4],
                                         uint32_t b0, uint32_t b1) {
    asm volatile("mma.sync.aligned.m16n8k16.row.col.f32.bf16.bf16.f32 "
        "{%0,%1,%2,%3}, {%4,%5,%6,%7}, {%8,%9}, {%0,%1,%2,%3};"
        : "+f"(d[0]), "+f"(d[1]), "+f"(d[2]), "+f"(d[3])
        : "r"(a[0]), "r"(a[1]), "r"(a[2]), "r"(a[3]), "r"(b0), "r"(b1));
}

// ---------------------------------------------------------------- normalize
__global__ void normalize_fq(const float* __restrict__ src) {
    int vec = blockIdx.x * 8 + (threadIdx.x >> 5);
    if (vec >= BB * M_REAL) return;
    int lane = threadIdx.x & 31;
    int b = vec / M_REAL, m = vec - b * M_REAL;
    const float2* s2 = (const float2*)(src + (size_t)vec * CC);
    __nv_bfloat162* d2 = (__nv_bfloat162*)(g_fq + ((size_t)b * M_PAD + m) * CC);
    float2 v[6]; float ss = 0.f;
#pragma unroll
    for (int i = 0; i < 6; i++) { v[i] = s2[lane + 32*i]; ss += v[i].x*v[i].x + v[i].y*v[i].y; }
#pragma unroll
    for (int o = 16; o > 0; o >>= 1) ss += __shfl_xor_sync(0xffffffffu, ss, o);
    float inv = 1.0f / fmaxf(sqrtf(ss), 1e-8f);
#pragma unroll
    for (int i = 0; i < 6; i++)
        d2[lane + 32*i] = __floats2bfloat162_rn(v[i].x * inv, v[i].y * inv);
}

__global__ void normalize_fs(const float* __restrict__ src) {
    int vec = blockIdx.x * 8 + (threadIdx.x >> 5);
    if (vec >= BB * NN * SS) return;
    int lane = threadIdx.x & 31;
    int b = vec / (NN * SS); int rem = vec - b * NN * SS;
    int n = rem / SS, s = rem - n * SS;
    const float2* s2 = (const float2*)(src + (size_t)vec * CC);
    __nv_bfloat162* d2 = (__nv_bfloat162*)(g_fs + (((size_t)(b * NN + n)) * S_PAD + s) * CC);
    float2 v[6]; float ss = 0.f;
#pragma unroll
    for (int i = 0; i < 6; i++) { v[i] = s2[lane + 32*i]; ss += v[i].x*v[i].x + v[i].y*v[i].y; }
#pragma unroll
    for (int o = 16; o > 0; o >>= 1) ss += __shfl_xor_sync(0xffffffffu, ss, o);
    float inv = 1.0f / fmaxf(sqrtf(ss), 1e-8f);
#pragma unroll
    for (int i = 0; i < 6; i++)
        d2[lane + 32*i] = __floats2bfloat162_rn(v[i].x * inv, v[i].y * inv);
}

__global__ void zero_kernel(float* __restrict__ out, int n) {
    int i = blockIdx.x * 256 + threadIdx.x;
    if (i < n) out[i] = 0.f;
}

// ---------------------------------------------------------------- sim (HMMA)
// CTA: 128 query rows x one (b,n). A resident (6 x K64 SW128 chunks, 96KB),
// B streamed in 12 batches of 4 chunks through an 8-stage ring; one wait+sync
// per batch. Per chunk: all A fragments hoisted, B fragments double-buffered
// across ks steps. 8 warps: warp_m = wid&1 (64 rows), warp_n = wid>>1 (32 cols).
__global__ __launch_bounds__(256, 1)
void sim_kernel(float* __restrict__ logits) {
    extern __shared__ char smem[];
    const uint32_t sb = smem_u32(smem);
    float* red = (float*)(smem + RED_OFF);

    const int tid = threadIdx.x, lane = tid & 31, wid = tid >> 5;
    const int warp_m = wid & 1, warp_n = wid >> 1;
    const int mt = blockIdx.x, n = blockIdx.y, b = blockIdx.z;
    const int m0 = mt * 128;

    // cp.async mapping: thread -> row tid/2, 64B half (tid&1), 4x 16B segs
    const int ld_row = tid >> 1;
    const int ld_half = (tid & 1);

    // ---- preload resident A (one commit group): 6 chunks x 16KB ----
    {
        const __nv_bfloat16* Ar = g_fq + ((size_t)b * M_PAD + m0 + ld_row) * CC;
#pragma unroll
        for (int kc = 0; kc < KCH; kc++) {
            const __nv_bfloat16* src = Ar + kc * 64 + ld_half * 32;
            uint32_t cbase = sb + A_OFF + kc * CHUNK_B;
#pragma unroll
            for (int s = 0; s < 4; s++) {
                uint32_t off = (uint32_t)ld_row * 128 + ld_half * 64 + s * 16;
                CP_ASYNC16(cbase + SWZ(off), __cvta_generic_to_global(src + s * 8));
            }
        }
        CP_COMMIT();
    }
    const __nv_bfloat16* Bb = g_fs + ((size_t)(b * NN + n)) * S_PAD * CC;
    auto issueBatch = [&](int g) {
#pragma unroll
        for (int i = 0; i < BATCH; i++) {
            int j = g * BATCH + i;
            int st = j / KCH, kc = j - st * KCH;
            const __nv_bfloat16* src =
                Bb + ((size_t)(st * 128 + ld_row)) * CC + kc * 64 + ld_half * 32;
            uint32_t cbase = sb + B_OFF + ((uint32_t)((g & 1) * BATCH + i)) * CHUNK_B;
#pragma unroll
            for (int s = 0; s < 4; s++) {
                uint32_t off = (uint32_t)ld_row * 128 + ld_half * 64 + s * 16;
                CP_ASYNC16(cbase + SWZ(off), __cvta_generic_to_global(src + s * 8));
            }
        }
        CP_COMMIT();
    };
    issueBatch(0); issueBatch(1);
    CP_WAITN(1);            // A + batch0 landed (batch1 in flight)
    __syncthreads();

    // ldmatrix addressing in SW128 chunks
    const uint32_t a_row = (uint32_t)(warp_m * 64 + (lane & 15));
    const uint32_t a_seg0 = (uint32_t)(lane >> 4) * 16;
    const uint32_t b_row = (uint32_t)(warp_n * 32 + ((lane >> 4) << 3) + (lane & 7));
    const uint32_t b_seg0 = (uint32_t)((lane >> 3) & 1) * 16;

    float rmax[4][2];
#pragma unroll
    for (int mf = 0; mf < 4; mf++) { rmax[mf][0] = -1e30f; rmax[mf][1] = -1e30f; }

    float acc[4][4][4];

    for (int g = 0; g < NB; g++) {
#pragma unroll
        for (int i = 0; i < BATCH; i++) {
            const int j = g * BATCH + i;
            const int st = j / KCH, kc = j - st * KCH;
            const int slot = (g & 1) * BATCH + i;

            if (kc == 0) {
#pragma unroll
                for (int mf = 0; mf < 4; mf++)
#pragma unroll
                    for (int nf = 0; nf < 4; nf++)
#pragma unroll
                        for (int c = 0; c < 4; c++) acc[mf][nf][c] = 0.f;
            }

            const uint32_t Ach = sb + A_OFF + kc * CHUNK_B;
            const uint32_t Bch = sb + B_OFF + slot * CHUNK_B;

            // hoist ALL A fragments for this chunk (A resident, no hazards)
            uint32_t a_all[4][4][4];   // [ks][mf][frag]
#pragma unroll
            for (int ks = 0; ks < 4; ks++)
#pragma unroll
                for (int mf = 0; mf < 4; mf++) {
                    uint32_t row = a_row + mf * 16;
                    uint32_t xr = ((row & 7) << 4);
                    ldsm4(a_all[ks][mf], Ach + row * 128 + ((ks * 32 + a_seg0) ^ xr));
                }

            // double-buffered B fragments across ks
            uint32_t bf[2][2][4];      // [buf][p][frag]
#pragma unroll
            for (int p = 0; p < 2; p++) {
                uint32_t row = b_row + p * 16;
                uint32_t xr = ((row & 7) << 4);
                ldsm4(bf[0][p], Bch + row * 128 + ((0 * 32 + b_seg0) ^ xr));
            }
#pragma unroll
            for (int ks = 0; ks < 4; ks++) {
                const int cur = ks & 1, nxt = cur ^ 1;
                if (ks < 3) {
#pragma unroll
                    for (int p = 0; p < 2; p++) {
                        uint32_t row = b_row + p * 16;
                        uint32_t xr = ((row & 7) << 4);
                        ldsm4(bf[nxt][p],
                              Bch + row * 128 + (((ks + 1) * 32 + b_seg0) ^ xr));
                    }
                }
#pragma unroll
                for (int mf = 0; mf < 4; mf++)
#pragma unroll
                    for (int p = 0; p < 2; p++) {
                        mma16816(acc[mf][p*2+0], a_all[ks][mf], bf[cur][p][0], bf[cur][p][1]);
                        mma16816(acc[mf][p*2+1], a_all[ks][mf], bf[cur][p][2], bf[cur][p][3]);
                    }
            }

            if (kc == KCH - 1) {
                const int s0 = st * 128;
#pragma unroll
                for (int mf = 0; mf < 4; mf++)
#pragma unroll
                    for (int nf = 0; nf < 4; nf++) {
                        int colb = s0 + warp_n * 32 + nf * 8 + (lane & 3) * 2;
                        const float* c = acc[mf][nf];
                        if (colb < SS) {
                            rmax[mf][0] = fmaxf(rmax[mf][0], c[0]);
                            rmax[mf][1] = fmaxf(rmax[mf][1], c[2]);
                        }
                        if (colb + 1 < SS) {
                            rmax[mf][0] = fmaxf(rmax[mf][0], c[1]);
                            rmax[mf][1] = fmaxf(rmax[mf][1], c[3]);
                        }
                    }
            }
        }

        // one sync event per batch
        if (g + 1 < NB) {
            CP_WAITN(0);
            __syncthreads();
            if (g + 2 < NB) issueBatch(g + 2);
        }
    }

    // lane reduce (lanes xor 1, 2 share rows), write red[warp_n][row]
#pragma unroll
    for (int mf = 0; mf < 4; mf++)
#pragma unroll
        for (int r2 = 0; r2 < 2; r2++) {
            float v = rmax[mf][r2];
            v = fmaxf(v, __shfl_xor_sync(0xffffffffu, v, 1));
            v = fmaxf(v, __shfl_xor_sync(0xffffffffu, v, 2));
            if ((lane & 3) == 0) {
                int row = warp_m * 64 + mf * 16 + (lane >> 2) + r2 * 8;
                red[warp_n * 128 + row] = v;
            }
        }
    __syncthreads();

    if (tid < 128) {
        float v = fmaxf(fmaxf(red[tid], red[128 + tid]),
                        fmaxf(red[256 + tid], red[384 + tid]));
        int row = m0 + tid;
        if (row < M_REAL) {
            int q = row / TT;
            atomicAdd(logits + ((size_t)b * QQ + q) * NN + n, v * (1.0f / TT));
        }
    }
}

// ---------------------------------------------------------------- cls branch
__global__ void cls_kernel(const float* __restrict__ x_shot,
                           const float* __restrict__ x_query,
                           float* __restrict__ cls_out) {
    int w = blockIdx.x * 8 + (threadIdx.x >> 5);
    if (w >= BB * QQ * NN) return;
    int lane = threadIdx.x & 31;
    int n = w % NN;
    int q = (w / NN) % QQ;
    int b = w / (NN * QQ);
    const float* xq = x_query + ((size_t)b * QQ + q) * CC;
    const float* xs = x_shot + ((size_t)b * NN + n) * KSHOT * CC;
    float dot = 0.f, qss = 0.f, pss = 0.f;
#pragma unroll
    for (int i = 0; i < 12; i++) {
        int c = lane + 32 * i;
        float xv = xq[c];
        float pv = 0.f;
#pragma unroll
        for (int kk = 0; kk < KSHOT; kk++) pv += xs[kk * CC + c];
        pv *= (1.0f / KSHOT);
        dot += xv * pv; qss += xv * xv; pss += pv * pv;
    }
#pragma unroll
    for (int o = 16; o > 0; o >>= 1) {
        dot += __shfl_xor_sync(0xffffffffu, dot, o);
        qss += __shfl_xor_sync(0xffffffffu, qss, o);
        pss += __shfl_xor_sync(0xffffffffu, pss, o);
    }
    if (lane == 0) {
        cls_out[(b * QQ + q) * NN + n] = TEMP_V * dot /
            (fmaxf(sqrtf(qss), 1e-12f) * fmaxf(sqrtf(pss), 1e-12f));
    }
}

// ----------------------------------------------------------------
extern "C" void kernel_launch(void* const* d_in, const int* in_sizes, int n_in,
                              void* d_out, int out_size) {
    const float* feat_shot  = (const float*)d_in[0];
    const float* feat_query = (const float*)d_in[1];
    const float* x_shot     = (const float*)d_in[2];
    const float* x_query    = (const float*)d_in[3];

    float* out    = (float*)d_out;
    float* logits = out;                 // [b,q,n] = 750
    float* cls    = out + BB * QQ * NN;  // [b,q,n] = 750

    int nvq = BB * M_REAL;        // 29400
    int nvs = BB * NN * SS;       // 9800
    normalize_fq<<<(nvq + 7) / 8, 256>>>(feat_query);
    normalize_fs<<<(nvs + 7) / 8, 256>>>(feat_shot);

    zero_kernel<<<(BB * QQ * NN + 255) / 256, 256>>>(logits, BB * QQ * NN);

    cudaFuncSetAttribute(sim_kernel,
                         cudaFuncAttributeMaxDynamicSharedMemorySize, SMEM_TOTAL);
    dim3 grid(M_TILES, NN, BB);   // (115, 5, 2)
    sim_kernel<<<grid, 256, SMEM_TOTAL>>>(logits);

    int nw = BB * QQ * NN;        // 750 warps
    cls_kernel<<<(nw + 7) / 8, 256>>>(x_shot, x_query, cls);
}

// round 16
// speedup vs baseline: 1.0499x; 1.0499x over previous
#include <cuda_runtime.h>
#include <cuda_bf16.h>
#include <cstdint>
#include <math.h>

// ---------------------------------------------------------------- shapes
#define BB 2
#define NN 5
#define KSHOT 5
#define QQ 75
#define TT 196
#define CC 384
#define SS 980
#define M_REAL (QQ*TT)      // 14700
#define M_PAD  14720        // 115*128, padded rows zero (BSS)
#define S_PAD  1024         // 4*256, padded rows zero (BSS)
#define M_TILES 115
#define S_TILES 4           // N-tiles of 256 shot tokens
#define KCH 6               // K chunks of 64 bf16 (128B rows, SW128 atoms)
#define NCHUNK (S_TILES*KCH)  // 24 B chunks
#define BATCH 2             // chunks per sync event
#define NB (NCHUNK/BATCH)   // 12 batches
#define NSTAGE 4            // B ring stages (2 batches resident)
#define TEMP_V 10.0f

// SW128 chunks. A chunk: 128 rows x 128B. B chunk: 256 rows x 128B.
#define A_CH 16384
#define B_CH 32768
#define A_OFF 0
#define B_OFF (KCH*A_CH)                   // 98304 (A resident: 96KB)
#define SMEM_TOTAL (B_OFF + NSTAGE*B_CH)   // 229376 <= 232448 max dyn
// reduction scratch reuses the B ring after the mainloop (8*128 floats)
#define RED_OFF B_OFF

// normalized bf16 scratch, zero-padded (BSS zero-init)
__device__ __nv_bfloat16 g_fq[(size_t)BB*M_PAD*CC];
__device__ __nv_bfloat16 g_fs[(size_t)BB*NN*S_PAD*CC];

// ---------------------------------------------------------------- helpers
__device__ __forceinline__ uint32_t smem_u32(const void* p) {
    uint32_t a;
    asm("{ .reg .u64 t; cvta.to.shared.u64 t, %1; cvt.u32.u64 %0, t; }"
        : "=r"(a) : "l"(p));
    return a;
}
#define SWZ(off) ((off) ^ (((off) >> 3) & 0x70))

#define CP_ASYNC16(dst, gsrc) \
    asm volatile("cp.async.cg.shared.global [%0], [%1], 16;" :: "r"(dst), "l"(gsrc) : "memory")
#define CP_COMMIT() asm volatile("cp.async.commit_group;" ::: "memory")
#define CP_WAITN(n) asm volatile("cp.async.wait_group %0;" :: "n"(n) : "memory")

__device__ __forceinline__ void ldsm4(uint32_t (&r)[4], uint32_t addr) {
    asm volatile("ldmatrix.sync.aligned.m8n8.x4.shared.b16 {%0,%1,%2,%3}, [%4];"
        : "=r"(r[0]), "=r"(r[1]), "=r"(r[2]), "=r"(r[3]) : "r"(addr));
}
__device__ __forceinline__ void mma16816(float (&d)[4], const uint32_t (&a)[4],
                                         uint32_t b0, uint32_t b1) {
    asm volatile("mma.sync.aligned.m16n8k16.row.col.f32.bf16.bf16.f32 "
        "{%0,%1,%2,%3}, {%4,%5,%6,%7}, {%8,%9}, {%0,%1,%2,%3};"
        : "+f"(d[0]), "+f"(d[1]), "+f"(d[2]), "+f"(d[3])
        : "r"(a[0]), "r"(a[1]), "r"(a[2]), "r"(a[3]), "r"(b0), "r"(b1));
}

// ---------------------------------------------------------------- normalize
__global__ void normalize_fq(const float* __restrict__ src) {
    int vec = blockIdx.x * 8 + (threadIdx.x >> 5);
    if (vec >= BB * M_REAL) return;
    int lane = threadIdx.x & 31;
    int b = vec / M_REAL, m = vec - b * M_REAL;
    const float2* s2 = (const float2*)(src + (size_t)vec * CC);
    __nv_bfloat162* d2 = (__nv_bfloat162*)(g_fq + ((size_t)b * M_PAD + m) * CC);
    float2 v[6]; float ss = 0.f;
#pragma unroll
    for (int i = 0; i < 6; i++) { v[i] = s2[lane + 32*i]; ss += v[i].x*v[i].x + v[i].y*v[i].y; }
#pragma unroll
    for (int o = 16; o > 0; o >>= 1) ss += __shfl_xor_sync(0xffffffffu, ss, o);
    float inv = 1.0f / fmaxf(sqrtf(ss), 1e-8f);
#pragma unroll
    for (int i = 0; i < 6; i++)
        d2[lane + 32*i] = __floats2bfloat162_rn(v[i].x * inv, v[i].y * inv);
}

__global__ void normalize_fs(const float* __restrict__ src) {
    int vec = blockIdx.x * 8 + (threadIdx.x >> 5);
    if (vec >= BB * NN * SS) return;
    int lane = threadIdx.x & 31;
    int b = vec / (NN * SS); int rem = vec - b * NN * SS;
    int n = rem / SS, s = rem - n * SS;
    const float2* s2 = (const float2*)(src + (size_t)vec * CC);
    __nv_bfloat162* d2 = (__nv_bfloat162*)(g_fs + (((size_t)(b * NN + n)) * S_PAD + s) * CC);
    float2 v[6]; float ss = 0.f;
#pragma unroll
    for (int i = 0; i < 6; i++) { v[i] = s2[lane + 32*i]; ss += v[i].x*v[i].x + v[i].y*v[i].y; }
#pragma unroll
    for (int o = 16; o > 0; o >>= 1) ss += __shfl_xor_sync(0xffffffffu, ss, o);
    float inv = 1.0f / fmaxf(sqrtf(ss), 1e-8f);
#pragma unroll
    for (int i = 0; i < 6; i++)
        d2[lane + 32*i] = __floats2bfloat162_rn(v[i].x * inv, v[i].y * inv);
}

__global__ void zero_kernel(float* __restrict__ out, int n) {
    int i = blockIdx.x * 256 + threadIdx.x;
    if (i < n) out[i] = 0.f;
}

// ---------------------------------------------------------------- sim (HMMA)
// CTA: 128 query rows x one (b,n), N-tile = 256 shot tokens per s-tile.
// A resident (6 x K64 SW128 chunks, 96KB); B streamed in 12 batches of 2
// chunks of [256 rows][64 k] through a 4-stage ring (one wait+sync per batch).
// 16 warps: warp_m = wid&1 (64 rows), warp_n = wid>>1 (32 of 256 cols) —
// every warp keeps the proven 64x32 tile / MMA:ldsm ratio.
__global__ __launch_bounds__(512, 1)
void sim_kernel(float* __restrict__ logits) {
    extern __shared__ char smem[];
    const uint32_t sb = smem_u32(smem);
    float* red = (float*)(smem + RED_OFF);

    const int tid = threadIdx.x, lane = tid & 31, wid = tid >> 5;
    const int warp_m = wid & 1, warp_n = wid >> 1;   // 0..7
    const int mt = blockIdx.x, n = blockIdx.y, b = blockIdx.z;
    const int m0 = mt * 128;

    // ---- preload resident A: thread -> row tid/4, quarter (tid&3)*32B ----
    {
        const int arow = tid >> 2, aq = tid & 3;
        const __nv_bfloat16* Ar = g_fq + ((size_t)b * M_PAD + m0 + arow) * CC;
#pragma unroll
        for (int kc = 0; kc < KCH; kc++) {
            const __nv_bfloat16* src = Ar + kc * 64 + aq * 16;
            uint32_t cbase = sb + A_OFF + kc * A_CH;
#pragma unroll
            for (int s = 0; s < 2; s++) {
                uint32_t off = (uint32_t)arow * 128 + aq * 32 + s * 16;
                CP_ASYNC16(cbase + SWZ(off), __cvta_generic_to_global(src + s * 8));
            }
        }
        CP_COMMIT();
    }
    // B: chunk = 256 rows x 128B = 32KB; 512 threads -> 64B each = 4x 16B segs
    const int ld_row = tid >> 1;          // 0..255
    const int ld_half = (tid & 1);        // which 64B half of the 128B row
    const __nv_bfloat16* Bb = g_fs + ((size_t)(b * NN + n)) * S_PAD * CC;
    auto issueBatch = [&](int g) {
#pragma unroll
        for (int i = 0; i < BATCH; i++) {
            int j = g * BATCH + i;
            int st = j / KCH, kc = j - st * KCH;
            const __nv_bfloat16* src =
                Bb + ((size_t)(st * 256 + ld_row)) * CC + kc * 64 + ld_half * 32;
            uint32_t cbase = sb + B_OFF + ((uint32_t)((g & 1) * BATCH + i)) * B_CH;
#pragma unroll
            for (int s = 0; s < 4; s++) {   // FIXED: 4 segs (64B per thread)
                uint32_t off = (uint32_t)ld_row * 128 + ld_half * 64 + s * 16;
                CP_ASYNC16(cbase + SWZ(off), __cvta_generic_to_global(src + s * 8));
            }
        }
        CP_COMMIT();
    };
    issueBatch(0); issueBatch(1);
    CP_WAITN(1);            // A + batch0 landed (batch1 in flight)
    __syncthreads();

    // ldmatrix addressing in SW128 chunks
    const uint32_t a_row = (uint32_t)(warp_m * 64 + (lane & 15));
    const uint32_t a_seg0 = (uint32_t)(lane >> 4) * 16;
    const uint32_t b_row = (uint32_t)(warp_n * 32 + ((lane >> 4) << 3) + (lane & 7));
    const uint32_t b_seg0 = (uint32_t)((lane >> 3) & 1) * 16;

    float rmax[4][2];
#pragma unroll
    for (int mf = 0; mf < 4; mf++) { rmax[mf][0] = -1e30f; rmax[mf][1] = -1e30f; }

    float acc[4][4][4];

    for (int g = 0; g < NB; g++) {
#pragma unroll
        for (int i = 0; i < BATCH; i++) {
            const int j = g * BATCH + i;
            const int st = j / KCH, kc = j - st * KCH;
            const int slot = (g & 1) * BATCH + i;

            if (kc == 0) {
#pragma unroll
                for (int mf = 0; mf < 4; mf++)
#pragma unroll
                    for (int nf = 0; nf < 4; nf++)
#pragma unroll
                        for (int c = 0; c < 4; c++) acc[mf][nf][c] = 0.f;
            }

            const uint32_t Ach = sb + A_OFF + kc * A_CH;
            const uint32_t Bch = sb + B_OFF + slot * B_CH;
#pragma unroll
            for (int ks = 0; ks < 4; ks++) {
                uint32_t a[4][4];
#pragma unroll
                for (int mf = 0; mf < 4; mf++) {
                    uint32_t row = a_row + mf * 16;
                    uint32_t xr = ((row & 7) << 4);
                    ldsm4(a[mf], Ach + row * 128 + ((ks * 32 + a_seg0) ^ xr));
                }
                uint32_t bf[2][4];
#pragma unroll
                for (int p = 0; p < 2; p++) {
                    uint32_t row = b_row + p * 16;
                    uint32_t xr = ((row & 7) << 4);
                    ldsm4(bf[p], Bch + row * 128 + ((ks * 32 + b_seg0) ^ xr));
                }
#pragma unroll
                for (int mf = 0; mf < 4; mf++)
#pragma unroll
                    for (int p = 0; p < 2; p++) {
                        mma16816(acc[mf][p*2+0], a[mf], bf[p][0], bf[p][1]);
                        mma16816(acc[mf][p*2+1], a[mf], bf[p][2], bf[p][3]);
                    }
            }

            if (kc == KCH - 1) {
                const int s0 = st * 256;
#pragma unroll
                for (int mf = 0; mf < 4; mf++)
#pragma unroll
                    for (int nf = 0; nf < 4; nf++) {
                        int colb = s0 + warp_n * 32 + nf * 8 + (lane & 3) * 2;
                        const float* c = acc[mf][nf];
                        if (colb < SS) {
                            rmax[mf][0] = fmaxf(rmax[mf][0], c[0]);
                            rmax[mf][1] = fmaxf(rmax[mf][1], c[2]);
                        }
                        if (colb + 1 < SS) {
                            rmax[mf][0] = fmaxf(rmax[mf][0], c[1]);
                            rmax[mf][1] = fmaxf(rmax[mf][1], c[3]);
                        }
                    }
            }
        }

        // one sync event per batch
        if (g + 1 < NB) {
            CP_WAITN(0);
            __syncthreads();
            if (g + 2 < NB) issueBatch(g + 2);
        }
    }

    // mainloop done; B ring is dead -> reuse as reduction scratch
    __syncthreads();

    // lane reduce (lanes xor 1, 2 share rows), write red[warp_n][row]
#pragma unroll
    for (int mf = 0; mf < 4; mf++)
#pragma unroll
        for (int r2 = 0; r2 < 2; r2++) {
            float v = rmax[mf][r2];
            v = fmaxf(v, __shfl_xor_sync(0xffffffffu, v, 1));
            v = fmaxf(v, __shfl_xor_sync(0xffffffffu, v, 2));
            if ((lane & 3) == 0) {
                int row = warp_m * 64 + mf * 16 + (lane >> 2) + r2 * 8;
                red[warp_n * 128 + row] = v;
            }
        }
    __syncthreads();

    if (tid < 128) {
        float v = red[tid];
#pragma unroll
        for (int gq = 1; gq < 8; gq++) v = fmaxf(v, red[gq * 128 + tid]);
        int row = m0 + tid;
        if (row < M_REAL) {
            int q = row / TT;
            atomicAdd(logits + ((size_t)b * QQ + q) * NN + n, v * (1.0f / TT));
        }
    }
}

// ---------------------------------------------------------------- cls branch
__global__ void cls_kernel(const float* __restrict__ x_shot,
                           const float* __restrict__ x_query,
                           float* __restrict__ cls_out) {
    int w = blockIdx.x * 8 + (threadIdx.x >> 5);
    if (w >= BB * QQ * NN) return;
    int lane = threadIdx.x & 31;
    int n = w % NN;
    int q = (w / NN) % QQ;
    int b = w / (NN * QQ);
    const float* xq = x_query + ((size_t)b * QQ + q) * CC;
    const float* xs = x_shot + ((size_t)b * NN + n) * KSHOT * CC;
    float dot = 0.f, qss = 0.f, pss = 0.f;
#pragma unroll
    for (int i = 0; i < 12; i++) {
        int c = lane + 32 * i;
        float xv = xq[c];
        float pv = 0.f;
#pragma unroll
        for (int kk = 0; kk < KSHOT; kk++) pv += xs[kk * CC + c];
        pv *= (1.0f / KSHOT);
        dot += xv * pv; qss += xv * xv; pss += pv * pv;
    }
#pragma unroll
    for (int o = 16; o > 0; o >>= 1) {
        dot += __shfl_xor_sync(0xffffffffu, dot, o);
        qss += __shfl_xor_sync(0xffffffffu, qss, o);
        pss += __shfl_xor_sync(0xffffffffu, pss, o);
    }
    if (lane == 0) {
        cls_out[(b * QQ + q) * NN + n] = TEMP_V * dot /
            (fmaxf(sqrtf(qss), 1e-12f) * fmaxf(sqrtf(pss), 1e-12f));
    }
}

// ----------------------------------------------------------------
extern "C" void kernel_launch(void* const* d_in, const int* in_sizes, int n_in,
                              void* d_out, int out_size) {
    const float* feat_shot  = (const float*)d_in[0];
    const float* feat_query = (const float*)d_in[1];
    const float* x_shot     = (const float*)d_in[2];
    const float* x_query    = (const float*)d_in[3];

    float* out    = (float*)d_out;
    float* logits = out;                 // [b,q,n] = 750
    float* cls    = out + BB * QQ * NN;  // [b,q,n] = 750

    int nvq = BB * M_REAL;        // 29400
    int nvs = BB * NN * SS;       // 9800
    normalize_fq<<<(nvq + 7) / 8, 256>>>(feat_query);
    normalize_fs<<<(nvs + 7) / 8, 256>>>(feat_shot);

    zero_kernel<<<(BB * QQ * NN + 255) / 256, 256>>>(logits, BB * QQ * NN);

    cudaFuncSetAttribute(sim_kernel,
                         cudaFuncAttributeMaxDynamicSharedMemorySize, SMEM_TOTAL);
    dim3 grid(M_TILES, NN, BB);   // (115, 5, 2)
    sim_kernel<<<grid, 512, SMEM_TOTAL>>>(logits);

    int nw = BB * QQ * NN;        // 750 warps
    cls_kernel<<<(nw + 7) / 8, 256>>>(x_shot, x_query, cls);
}